// round 2
// baseline (speedup 1.0000x reference)
#include <cuda_runtime.h>
#include <cstdint>

#define NN 50000
#define NE 500000
#define DD 256

#define BM 128
#define BN 256
#define BK 16

// Scratch (static __device__ — no allocations allowed in kernel_launch)
__device__ __align__(16) float g_xa[(size_t)NN * DD];   // x @ W1a + b1
__device__ __align__(16) float g_agg[(size_t)NN * DD];  // scatter-sum of h
__device__ float g_cnt[NN];                              // in-degree counts -> 1/max(cnt,1)

// ---------------------------------------------------------------------------
__global__ void zero_kernel() {
    int stride = gridDim.x * blockDim.x;
    int tid = blockIdx.x * blockDim.x + threadIdx.x;
    for (int i = tid; i < NN * DD; i += stride) g_agg[i] = 0.0f;
    for (int i = tid; i < NN; i += stride) g_cnt[i] = 0.0f;
}

__global__ void rinv_kernel() {
    int i = blockIdx.x * blockDim.x + threadIdx.x;
    if (i < NN) g_cnt[i] = 1.0f / fmaxf(g_cnt[i], 1.0f);
}

// ---------------------------------------------------------------------------
// GEMM 1: g_xa = x @ W1[0:256,:] + b1          (M=NN, N=256, K=256)
// ---------------------------------------------------------------------------
__global__ __launch_bounds__(256, 1)
void xa_kernel(const float* __restrict__ x, const float* __restrict__ W1,
               const float* __restrict__ b1) {
    __shared__ __align__(16) float As[BK][BM];
    __shared__ __align__(16) float Bs[BK][BN];

    const int tid = threadIdx.x;
    const int trow = tid >> 4;   // 0..15  (M direction, 8 rows each)
    const int tcol = tid & 15;   // 0..15  (N direction, 4x4 strided cols)
    const int m0 = blockIdx.x * BM;

    float4 ar[2], br[4];

    auto loadA = [&](int kt) {
#pragma unroll
        for (int j = 0; j < 2; j++) {
            int i = tid + j * 256;
            int arow = i >> 2, ac4 = i & 3;
            int m = m0 + arow;
            if (m < NN)
                ar[j] = *(const float4*)&x[(size_t)m * DD + kt + ac4 * 4];
            else
                ar[j] = make_float4(0.f, 0.f, 0.f, 0.f);
        }
    };
    auto loadB = [&](int kt) {
#pragma unroll
        for (int j = 0; j < 4; j++) {
            int i = tid + j * 256;
            int brow = i >> 6, bc4 = i & 63;
            br[j] = *(const float4*)&W1[(size_t)(kt + brow) * DD + bc4 * 4];
        }
    };
    auto store_tile = [&]() {
#pragma unroll
        for (int j = 0; j < 2; j++) {
            int i = tid + j * 256;
            int arow = i >> 2, ac4 = i & 3;
            As[ac4 * 4 + 0][arow] = ar[j].x;
            As[ac4 * 4 + 1][arow] = ar[j].y;
            As[ac4 * 4 + 2][arow] = ar[j].z;
            As[ac4 * 4 + 3][arow] = ar[j].w;
        }
#pragma unroll
        for (int j = 0; j < 4; j++) {
            int i = tid + j * 256;
            int brow = i >> 6, bc4 = i & 63;
            *(float4*)&Bs[brow][bc4 * 4] = br[j];
        }
    };

    float acc[8][16];
#pragma unroll
    for (int a = 0; a < 8; a++)
#pragma unroll
        for (int b = 0; b < 16; b++) acc[a][b] = 0.0f;

    auto compute_tile = [&]() {
#pragma unroll
        for (int k = 0; k < BK; k++) {
            float4 a0 = *(const float4*)&As[k][trow * 8];
            float4 a1 = *(const float4*)&As[k][trow * 8 + 4];
            float av[8] = {a0.x, a0.y, a0.z, a0.w, a1.x, a1.y, a1.z, a1.w};
#pragma unroll
            for (int h = 0; h < 4; h++) {
                float4 b4 = *(const float4*)&Bs[k][h * 64 + tcol * 4];
                float bv[4] = {b4.x, b4.y, b4.z, b4.w};
#pragma unroll
                for (int mi = 0; mi < 8; mi++)
#pragma unroll
                    for (int j = 0; j < 4; j++)
                        acc[mi][h * 4 + j] = fmaf(av[mi], bv[j], acc[mi][h * 4 + j]);
            }
        }
    };

    const int T = DD / BK;  // 16
    loadA(0); loadB(0);
    for (int t = 0; t < T; t++) {
        store_tile();
        __syncthreads();
        if (t + 1 < T) { loadA((t + 1) * BK); loadB((t + 1) * BK); }
        compute_tile();
        __syncthreads();
    }

#pragma unroll
    for (int mi = 0; mi < 8; mi++) {
        int m = m0 + trow * 8 + mi;
        if (m < NN) {
#pragma unroll
            for (int h = 0; h < 4; h++) {
                int n = h * 64 + tcol * 4;
                float4 bb = *(const float4*)&b1[n];
                float4 v;
                v.x = acc[mi][h * 4 + 0] + bb.x;
                v.y = acc[mi][h * 4 + 1] + bb.y;
                v.z = acc[mi][h * 4 + 2] + bb.z;
                v.w = acc[mi][h * 4 + 3] + bb.w;
                *(float4*)&g_xa[(size_t)m * DD + n] = v;
            }
        }
    }
}

// ---------------------------------------------------------------------------
// GEMM 2 (fused): for edge tile: eb = edge_attr @ W1[256:512,:]
//   h = relu(eb + g_xa[row])       (b1 already folded into g_xa)
//   g_agg[col] += h  (vector red), g_cnt[col] += 1
// edge_index is INT32 (jax x64 disabled): eidx[0..NE) = row, eidx[NE..2NE) = col
// ---------------------------------------------------------------------------
__global__ __launch_bounds__(256, 1)
void edge_kernel(const float* __restrict__ ea, const int* __restrict__ eidx,
                 const float* __restrict__ W1b) {
    __shared__ __align__(16) float As[BK][BM];
    __shared__ __align__(16) float Bs[BK][BN];
    __shared__ int rs[BM];
    __shared__ int cs[BM];

    const int tid = threadIdx.x;
    const int trow = tid >> 4;
    const int tcol = tid & 15;
    const int m0 = blockIdx.x * BM;

    if (tid < BM) {
        int m = m0 + tid;
        if (m < NE) {
            rs[tid] = eidx[m];        // source node
            cs[tid] = eidx[NE + m];   // destination node
        }
    }

    float4 ar[2], br[4];

    auto loadA = [&](int kt) {
#pragma unroll
        for (int j = 0; j < 2; j++) {
            int i = tid + j * 256;
            int arow = i >> 2, ac4 = i & 3;
            int m = m0 + arow;
            if (m < NE)
                ar[j] = *(const float4*)&ea[(size_t)m * DD + kt + ac4 * 4];
            else
                ar[j] = make_float4(0.f, 0.f, 0.f, 0.f);
        }
    };
    auto loadB = [&](int kt) {
#pragma unroll
        for (int j = 0; j < 4; j++) {
            int i = tid + j * 256;
            int brow = i >> 6, bc4 = i & 63;
            br[j] = *(const float4*)&W1b[(size_t)(kt + brow) * DD + bc4 * 4];
        }
    };
    auto store_tile = [&]() {
#pragma unroll
        for (int j = 0; j < 2; j++) {
            int i = tid + j * 256;
            int arow = i >> 2, ac4 = i & 3;
            As[ac4 * 4 + 0][arow] = ar[j].x;
            As[ac4 * 4 + 1][arow] = ar[j].y;
            As[ac4 * 4 + 2][arow] = ar[j].z;
            As[ac4 * 4 + 3][arow] = ar[j].w;
        }
#pragma unroll
        for (int j = 0; j < 4; j++) {
            int i = tid + j * 256;
            int brow = i >> 6, bc4 = i & 63;
            *(float4*)&Bs[brow][bc4 * 4] = br[j];
        }
    };

    float acc[8][16];
#pragma unroll
    for (int a = 0; a < 8; a++)
#pragma unroll
        for (int b = 0; b < 16; b++) acc[a][b] = 0.0f;

    auto compute_tile = [&]() {
#pragma unroll
        for (int k = 0; k < BK; k++) {
            float4 a0 = *(const float4*)&As[k][trow * 8];
            float4 a1 = *(const float4*)&As[k][trow * 8 + 4];
            float av[8] = {a0.x, a0.y, a0.z, a0.w, a1.x, a1.y, a1.z, a1.w};
#pragma unroll
            for (int h = 0; h < 4; h++) {
                float4 b4 = *(const float4*)&Bs[k][h * 64 + tcol * 4];
                float bv[4] = {b4.x, b4.y, b4.z, b4.w};
#pragma unroll
                for (int mi = 0; mi < 8; mi++)
#pragma unroll
                    for (int j = 0; j < 4; j++)
                        acc[mi][h * 4 + j] = fmaf(av[mi], bv[j], acc[mi][h * 4 + j]);
            }
        }
    };

    const int T = DD / BK;  // 16
    loadA(0); loadB(0);
    for (int t = 0; t < T; t++) {
        store_tile();
        __syncthreads();
        if (t + 1 < T) { loadA((t + 1) * BK); loadB((t + 1) * BK); }
        compute_tile();
        __syncthreads();
    }

    // Fused epilogue: gather xa[row], relu, vector-reduce into agg[col]
#pragma unroll
    for (int mi = 0; mi < 8; mi++) {
        int m = trow * 8 + mi;
        if (m0 + m < NE) {
            int row = rs[m];
            int col = cs[m];
            const float* xr = &g_xa[(size_t)row * DD];
            float* agr = &g_agg[(size_t)col * DD];
#pragma unroll
            for (int h = 0; h < 4; h++) {
                int n = h * 64 + tcol * 4;
                float4 xv = *(const float4*)&xr[n];
                float v0 = fmaxf(acc[mi][h * 4 + 0] + xv.x, 0.0f);
                float v1 = fmaxf(acc[mi][h * 4 + 1] + xv.y, 0.0f);
                float v2 = fmaxf(acc[mi][h * 4 + 2] + xv.z, 0.0f);
                float v3 = fmaxf(acc[mi][h * 4 + 3] + xv.w, 0.0f);
                asm volatile("red.global.add.v4.f32 [%0], {%1,%2,%3,%4};"
                             :: "l"(agr + n), "f"(v0), "f"(v1), "f"(v2), "f"(v3)
                             : "memory");
            }
        }
    }
    // one count per edge (this grid covers each edge exactly once)
    if (tid < BM && m0 + tid < NE) {
        atomicAdd(&g_cnt[cs[tid]], 1.0f);
    }
}

// ---------------------------------------------------------------------------
// GEMM 3: out = relu( x @ W2[0:256,:] + (agg * rinv) @ W2[256:512,:] + b2 )
//   K = 512 (first half from x, second half from g_agg scaled per-row)
// ---------------------------------------------------------------------------
__global__ __launch_bounds__(256, 1)
void out_kernel(const float* __restrict__ x, const float* __restrict__ W2,
                const float* __restrict__ b2, float* __restrict__ out) {
    __shared__ __align__(16) float As[BK][BM];
    __shared__ __align__(16) float Bs[BK][BN];
    __shared__ float s_rinv[BM];

    const int tid = threadIdx.x;
    const int trow = tid >> 4;
    const int tcol = tid & 15;
    const int m0 = blockIdx.x * BM;

    if (tid < BM) {
        int m = m0 + tid;
        s_rinv[tid] = (m < NN) ? g_cnt[m] : 0.0f;  // g_cnt holds 1/max(cnt,1)
    }
    __syncthreads();

    float4 ar[2], br[4];

    auto loadA = [&](int kt) {
#pragma unroll
        for (int j = 0; j < 2; j++) {
            int i = tid + j * 256;
            int arow = i >> 2, ac4 = i & 3;
            int m = m0 + arow;
            if (m < NN) {
                if (kt < DD) {
                    ar[j] = *(const float4*)&x[(size_t)m * DD + kt + ac4 * 4];
                } else {
                    float4 v = *(const float4*)&g_agg[(size_t)m * DD + (kt - DD) + ac4 * 4];
                    float s = s_rinv[arow];
                    v.x *= s; v.y *= s; v.z *= s; v.w *= s;
                    ar[j] = v;
                }
            } else {
                ar[j] = make_float4(0.f, 0.f, 0.f, 0.f);
            }
        }
    };
    auto loadB = [&](int kt) {
#pragma unroll
        for (int j = 0; j < 4; j++) {
            int i = tid + j * 256;
            int brow = i >> 6, bc4 = i & 63;
            br[j] = *(const float4*)&W2[(size_t)(kt + brow) * DD + bc4 * 4];
        }
    };
    auto store_tile = [&]() {
#pragma unroll
        for (int j = 0; j < 2; j++) {
            int i = tid + j * 256;
            int arow = i >> 2, ac4 = i & 3;
            As[ac4 * 4 + 0][arow] = ar[j].x;
            As[ac4 * 4 + 1][arow] = ar[j].y;
            As[ac4 * 4 + 2][arow] = ar[j].z;
            As[ac4 * 4 + 3][arow] = ar[j].w;
        }
#pragma unroll
        for (int j = 0; j < 4; j++) {
            int i = tid + j * 256;
            int brow = i >> 6, bc4 = i & 63;
            *(float4*)&Bs[brow][bc4 * 4] = br[j];
        }
    };

    float acc[8][16];
#pragma unroll
    for (int a = 0; a < 8; a++)
#pragma unroll
        for (int b = 0; b < 16; b++) acc[a][b] = 0.0f;

    auto compute_tile = [&]() {
#pragma unroll
        for (int k = 0; k < BK; k++) {
            float4 a0 = *(const float4*)&As[k][trow * 8];
            float4 a1 = *(const float4*)&As[k][trow * 8 + 4];
            float av[8] = {a0.x, a0.y, a0.z, a0.w, a1.x, a1.y, a1.z, a1.w};
#pragma unroll
            for (int h = 0; h < 4; h++) {
                float4 b4 = *(const float4*)&Bs[k][h * 64 + tcol * 4];
                float bv[4] = {b4.x, b4.y, b4.z, b4.w};
#pragma unroll
                for (int mi = 0; mi < 8; mi++)
#pragma unroll
                    for (int j = 0; j < 4; j++)
                        acc[mi][h * 4 + j] = fmaf(av[mi], bv[j], acc[mi][h * 4 + j]);
            }
        }
    };

    const int T = (2 * DD) / BK;  // 32 (K = 512)
    loadA(0); loadB(0);
    for (int t = 0; t < T; t++) {
        store_tile();
        __syncthreads();
        if (t + 1 < T) { loadA((t + 1) * BK); loadB((t + 1) * BK); }
        compute_tile();
        __syncthreads();
    }

#pragma unroll
    for (int mi = 0; mi < 8; mi++) {
        int m = m0 + trow * 8 + mi;
        if (m < NN) {
#pragma unroll
            for (int h = 0; h < 4; h++) {
                int n = h * 64 + tcol * 4;
                float4 bb = *(const float4*)&b2[n];
                float4 v;
                v.x = fmaxf(acc[mi][h * 4 + 0] + bb.x, 0.0f);
                v.y = fmaxf(acc[mi][h * 4 + 1] + bb.y, 0.0f);
                v.z = fmaxf(acc[mi][h * 4 + 2] + bb.z, 0.0f);
                v.w = fmaxf(acc[mi][h * 4 + 3] + bb.w, 0.0f);
                *(float4*)&out[(size_t)m * DD + n] = v;
            }
        }
    }
}

// ---------------------------------------------------------------------------
extern "C" void kernel_launch(void* const* d_in, const int* in_sizes, int n_in,
                              void* d_out, int out_size) {
    const float* x  = (const float*)d_in[0];
    const int* eix  = (const int*)d_in[1];   // int32! (jax x64 disabled)
    const float* ea = (const float*)d_in[2];
    // d_in[3] = u (unused), d_in[4] = batch (unused)
    const float* W1 = (const float*)d_in[5];
    const float* b1 = (const float*)d_in[6];
    const float* W2 = (const float*)d_in[7];
    const float* b2 = (const float*)d_in[8];
    float* out      = (float*)d_out;

    (void)in_sizes; (void)n_in; (void)out_size;

    zero_kernel<<<2048, 256>>>();
    xa_kernel<<<(NN + BM - 1) / BM, 256>>>(x, W1, b1);
    edge_kernel<<<(NE + BM - 1) / BM, 256>>>(ea, eix, W1 + (size_t)DD * DD);
    rinv_kernel<<<(NN + 255) / 256, 256>>>();
    out_kernel<<<(NN + BM - 1) / BM, 256>>>(x, W2, b2, out);
}

// round 4
// speedup vs baseline: 1.5329x; 1.5329x over previous
#include <cuda_runtime.h>
#include <cuda_bf16.h>
#include <cstdint>

#define NN 50000
#define NE 500000
#define DD 256
#define KW 512

// ---------------- static device scratch ----------------
__device__ __align__(16) float g_xa[(size_t)NN * DD];   // x @ W1a + b1
__device__ __align__(16) float g_agg[(size_t)NN * DD];  // scatter-sum
__device__ float g_cnt[NN];                             // counts -> 1/max(cnt,1)
// weights transposed to [w][n][k] bf16, hi and lo parts (w: 0=W1, 1=W2)
__device__ __align__(16) unsigned short g_wh[2u * 256u * KW];
__device__ __align__(16) unsigned short g_wl[2u * 256u * KW];

// ---------------- helpers ----------------
static __device__ __forceinline__ uint32_t smem_u32(const void* p) {
    uint32_t a;
    asm("{ .reg .u64 t; cvta.to.shared.u64 t, %1; cvt.u32.u64 %0, t; }" : "=r"(a) : "l"(p));
    return a;
}
static __device__ __forceinline__ uint32_t pack2(__nv_bfloat16 a, __nv_bfloat16 b) {
    return (uint32_t)__bfloat16_as_ushort(a) | ((uint32_t)__bfloat16_as_ushort(b) << 16);
}

#define LDSM4(r0, r1, r2, r3, addr)                                          \
    asm volatile("ldmatrix.sync.aligned.m8n8.x4.shared.b16 {%0,%1,%2,%3}, [%4];" \
                 : "=r"(r0), "=r"(r1), "=r"(r2), "=r"(r3) : "r"(addr))

#define MMA16816(d, a, b0, b1)                                               \
    asm volatile("mma.sync.aligned.m16n8k16.row.col.f32.bf16.bf16.f32 "      \
                 "{%0,%1,%2,%3},{%4,%5,%6,%7},{%8,%9},{%0,%1,%2,%3};"        \
                 : "+f"((d)[0]), "+f"((d)[1]), "+f"((d)[2]), "+f"((d)[3])    \
                 : "r"((a)[0]), "r"((a)[1]), "r"((a)[2]), "r"((a)[3]),       \
                   "r"(b0), "r"(b1))

// ---------------- tiny kernels ----------------
__global__ void zero_kernel() {
    int stride = gridDim.x * blockDim.x;
    int tid = blockIdx.x * blockDim.x + threadIdx.x;
    for (int i = tid; i < NN * DD; i += stride) g_agg[i] = 0.0f;
    for (int i = tid; i < NN; i += stride) g_cnt[i] = 0.0f;
}
__global__ void rinv_kernel() {
    int i = blockIdx.x * blockDim.x + threadIdx.x;
    if (i < NN) g_cnt[i] = 1.0f / fmaxf(g_cnt[i], 1.0f);
}
// transpose W[k][n] f32 -> [n][k] bf16 hi/lo
__global__ void prep_kernel(const float* __restrict__ W1, const float* __restrict__ W2) {
    int t = blockIdx.x * blockDim.x + threadIdx.x;
    if (t >= 2 * 64 * 256) return;
    int n = t & 255;
    int k0 = ((t >> 8) & 63) * 8;
    int w = t >> 14;
    const float* W = w ? W2 : W1;
#pragma unroll
    for (int i = 0; i < 8; i++) {
        int k = k0 + i;
        float v = W[(size_t)k * DD + n];
        __nv_bfloat16 h = __float2bfloat16(v);
        float r = v - __bfloat162float(h);
        size_t o = ((size_t)w * 256 + n) * KW + k;
        g_wh[o] = __bfloat16_as_ushort(h);
        g_wl[o] = __bfloat16_as_ushort(__float2bfloat16(r));
    }
}

// ---------------- HMMA GEMM ----------------
// MODE 0: g_xa = x @ W1a + b1                                (M=NN, K=256)
// MODE 1: h = relu(ea @ W1b + g_xa[row]); red into g_agg[col] (M=NE, K=256)
// MODE 2: out = relu(x @ W2a + (agg*rinv) @ W2b + b2)         (M=NN, K=512)
template <int MODE>
__global__ __launch_bounds__(256, 1)
void gemm_kernel(const float* __restrict__ x, const float* __restrict__ ea,
                 const int* __restrict__ eidx, const float* __restrict__ bias,
                 float* __restrict__ outp)
{
    // smem: A tiles 128x16 bf16 (hi,lo), B tiles 256x16 bf16 (hi,lo), swizzled
    __shared__ __align__(16) unsigned char sA[2][4096];
    __shared__ __align__(16) unsigned char sB[2][8192];
    __shared__ int rs[128], cs[128];
    __shared__ float srv[128];

    const int tid = threadIdx.x, lane = tid & 31, wid = tid >> 5;
    const int wm = wid >> 1, wn = wid & 1;   // warp grid 4(M) x 2(N)
    const int m0 = blockIdx.x * 128;

    if (MODE == 1 && tid < 128) {
        int e = min(m0 + tid, NE - 1);
        rs[tid] = eidx[e];
        cs[tid] = eidx[NE + e];
    }
    if (MODE == 2 && tid < 128) {
        int m = m0 + tid;
        srv[tid] = (m < NN) ? g_cnt[m] : 0.0f;
    }

    const uint32_t sAb[2] = { smem_u32(sA[0]), smem_u32(sA[1]) };
    const uint32_t sBb[2] = { smem_u32(sB[0]), smem_u32(sB[1]) };

    float4 aST[2];
    uint4  bST[4];

    auto loadStage = [&](int ks) {
#pragma unroll
        for (int j = 0; j < 2; j++) {
            int idx = tid + j * 256;
            int row = idx >> 2, kk = idx & 3;
            if (MODE == 1) {
                int gm = min(m0 + row, NE - 1);
                aST[j] = *(const float4*)&ea[(size_t)gm * DD + ks * 16 + kk * 4];
            } else if (MODE == 0) {
                int gm = min(m0 + row, NN - 1);
                aST[j] = *(const float4*)&x[(size_t)gm * DD + ks * 16 + kk * 4];
            } else {
                int gm = min(m0 + row, NN - 1);
                if (ks < 16) {
                    aST[j] = *(const float4*)&x[(size_t)gm * DD + ks * 16 + kk * 4];
                } else {
                    float4 v = *(const float4*)&g_agg[(size_t)gm * DD + (ks - 16) * 16 + kk * 4];
                    float s = srv[row];
                    v.x *= s; v.y *= s; v.z *= s; v.w *= s;
                    aST[j] = v;
                }
            }
        }
        const int w  = (MODE == 2) ? 1 : 0;
        const int kb = (MODE == 1) ? 256 + ks * 16 : ks * 16;
#pragma unroll
        for (int j = 0; j < 2; j++) {
            int idx = tid + j * 256;
            int n = idx >> 1, c = idx & 1;
            size_t o = ((size_t)w * 256 + n) * KW + kb + c * 8;
            bST[j]     = *(const uint4*)&g_wh[o];
            bST[2 + j] = *(const uint4*)&g_wl[o];
        }
    };
    auto storeStage = [&]() {
#pragma unroll
        for (int j = 0; j < 2; j++) {
            int idx = tid + j * 256;
            int row = idx >> 2, kk = idx & 3;
            int c = kk >> 1;
            uint32_t off = row * 32 + (((c ^ ((row >> 2) & 1)) << 4)) + (kk & 1) * 8;
            float4 v = aST[j];
            __nv_bfloat16 h0 = __float2bfloat16(v.x), h1 = __float2bfloat16(v.y);
            __nv_bfloat16 h2 = __float2bfloat16(v.z), h3 = __float2bfloat16(v.w);
            __nv_bfloat16 l0 = __float2bfloat16(v.x - __bfloat162float(h0));
            __nv_bfloat16 l1 = __float2bfloat16(v.y - __bfloat162float(h1));
            __nv_bfloat16 l2 = __float2bfloat16(v.z - __bfloat162float(h2));
            __nv_bfloat16 l3 = __float2bfloat16(v.w - __bfloat162float(h3));
            *(uint2*)(sA[0] + off) = make_uint2(pack2(h0, h1), pack2(h2, h3));
            *(uint2*)(sA[1] + off) = make_uint2(pack2(l0, l1), pack2(l2, l3));
        }
#pragma unroll
        for (int j = 0; j < 2; j++) {
            int idx = tid + j * 256;
            int n = idx >> 1, c = idx & 1;
            uint32_t off = n * 32 + ((c ^ ((n >> 2) & 1)) << 4);
            *(uint4*)(sB[0] + off) = bST[j];
            *(uint4*)(sB[1] + off) = bST[2 + j];
        }
    };

    float acc[2][16][4];
#pragma unroll
    for (int a = 0; a < 2; a++)
#pragma unroll
        for (int b = 0; b < 16; b++)
#pragma unroll
            for (int q = 0; q < 4; q++) acc[a][b][q] = 0.0f;

    auto compute = [&]() {
#pragma unroll
        for (int sp = 0; sp < 3; sp++) {
            const uint32_t Ab = sAb[sp == 2 ? 1 : 0];
            const uint32_t Bb = sBb[sp == 1 ? 1 : 0];
            uint32_t afr[2][4];
#pragma unroll
            for (int mi = 0; mi < 2; mi++) {
                int row = wm * 32 + mi * 16 + (lane & 7) + ((lane >> 3) & 1) * 8;
                int c = lane >> 4;
                uint32_t addr = Ab + row * 32 + ((c ^ ((row >> 2) & 1)) << 4);
                LDSM4(afr[mi][0], afr[mi][1], afr[mi][2], afr[mi][3], addr);
            }
#pragma unroll
            for (int np = 0; np < 8; np++) {
                int n = wn * 128 + np * 16 + (lane & 7) + ((lane >> 4) & 1) * 8;
                int c = (lane >> 3) & 1;
                uint32_t addr = Bb + n * 32 + ((c ^ ((n >> 2) & 1)) << 4);
                uint32_t bfr[4];
                LDSM4(bfr[0], bfr[1], bfr[2], bfr[3], addr);
#pragma unroll
                for (int mi = 0; mi < 2; mi++) {
                    MMA16816(acc[mi][np * 2 + 0], afr[mi], bfr[0], bfr[1]);
                    MMA16816(acc[mi][np * 2 + 1], afr[mi], bfr[2], bfr[3]);
                }
            }
        }
    };

    const int NK = (MODE == 2) ? 32 : 16;
    loadStage(0);
    for (int ks = 0; ks < NK; ks++) {
        storeStage();
        __syncthreads();
        if (ks + 1 < NK) loadStage(ks + 1);
        compute();
        __syncthreads();
    }

    // ---------------- epilogue ----------------
    // d-frag: thread holds (row lane>>2, cols 2*(lane&3)+{0,1}) regs {0,1};
    //         (row lane>>2+8, same cols) regs {2,3}
    const int colb = wn * 128 + (lane & 3) * 2;
    if (MODE == 1) {
#pragma unroll
        for (int mi = 0; mi < 2; mi++) {
#pragma unroll
            for (int h = 0; h < 2; h++) {
                int lr = wm * 32 + mi * 16 + (lane >> 2) + h * 8;
                bool valid = (m0 + lr < NE);
                if (!valid) continue;
                int srcr = rs[lr], dstc = cs[lr];
                const float* xr = &g_xa[(size_t)srcr * DD];
                float* ag = &g_agg[(size_t)dstc * DD];
#pragma unroll
                for (int nt = 0; nt < 16; nt++) {
                    int n = colb + nt * 8;
                    float2 xv = *(const float2*)&xr[n];
                    float v0 = fmaxf(acc[mi][nt][h * 2 + 0] + xv.x, 0.0f);
                    float v1 = fmaxf(acc[mi][nt][h * 2 + 1] + xv.y, 0.0f);
                    asm volatile("red.global.add.v2.f32 [%0], {%1,%2};"
                                 :: "l"(ag + n), "f"(v0), "f"(v1) : "memory");
                }
            }
        }
        if (tid < 128 && m0 + tid < NE) atomicAdd(&g_cnt[cs[tid]], 1.0f);
    } else {
#pragma unroll
        for (int mi = 0; mi < 2; mi++) {
#pragma unroll
            for (int h = 0; h < 2; h++) {
                int row = m0 + wm * 32 + mi * 16 + (lane >> 2) + h * 8;
                if (row >= NN) continue;
                float* dst = (MODE == 0) ? &g_xa[(size_t)row * DD] : &outp[(size_t)row * DD];
#pragma unroll
                for (int nt = 0; nt < 16; nt++) {
                    int n = colb + nt * 8;
                    float2 bb = *(const float2*)&bias[n];
                    float2 v;
                    v.x = acc[mi][nt][h * 2 + 0] + bb.x;
                    v.y = acc[mi][nt][h * 2 + 1] + bb.y;
                    if (MODE == 2) { v.x = fmaxf(v.x, 0.0f); v.y = fmaxf(v.y, 0.0f); }
                    *(float2*)&dst[n] = v;
                }
            }
        }
    }
}

// ---------------------------------------------------------------------------
extern "C" void kernel_launch(void* const* d_in, const int* in_sizes, int n_in,
                              void* d_out, int out_size) {
    const float* x  = (const float*)d_in[0];
    const int* eix  = (const int*)d_in[1];   // int32 (jax x64 disabled)
    const float* ea = (const float*)d_in[2];
    const float* W1 = (const float*)d_in[5];
    const float* b1 = (const float*)d_in[6];
    const float* W2 = (const float*)d_in[7];
    const float* b2 = (const float*)d_in[8];
    float* out      = (float*)d_out;
    (void)in_sizes; (void)n_in; (void)out_size;

    zero_kernel<<<2048, 256>>>();
    prep_kernel<<<128, 256>>>(W1, W2);
    gemm_kernel<0><<<(NN + 127) / 128, 256>>>(x, ea, eix, b1, nullptr);
    gemm_kernel<1><<<(NE + 127) / 128, 256>>>(x, ea, eix, b1, nullptr);
    rinv_kernel<<<(NN + 255) / 256, 256>>>();
    gemm_kernel<2><<<(NN + 127) / 128, 256>>>(x, ea, eix, b2, out);
}

// round 9
// speedup vs baseline: 2.1756x; 1.4192x over previous
#include <cuda_runtime.h>
#include <cuda_bf16.h>
#include <cstdint>

#define NN 50000
#define NE 500000
#define DD 256
#define KW 512

// ---------------- static device scratch ----------------
__device__ __align__(16) float g_xa[(size_t)NN * DD];   // x @ W1a + b1
__device__ __align__(16) float g_agg[(size_t)NN * DD];  // scatter-sum
__device__ float g_cnt[NN];                             // counts -> 1/max(cnt,1)
// weights transposed to [w][n][k] bf16, hi and lo parts (w: 0=W1, 1=W2)
__device__ __align__(16) unsigned short g_wh[2u * 256u * KW];
__device__ __align__(16) unsigned short g_wl[2u * 256u * KW];

// ---------------- helpers ----------------
static __device__ __forceinline__ uint32_t smem_u32(const void* p) {
    uint32_t a;
    asm("{ .reg .u64 t; cvta.to.shared.u64 t, %1; cvt.u32.u64 %0, t; }" : "=r"(a) : "l"(p));
    return a;
}
static __device__ __forceinline__ uint32_t pack2(__nv_bfloat16 a, __nv_bfloat16 b) {
    return (uint32_t)__bfloat16_as_ushort(a) | ((uint32_t)__bfloat16_as_ushort(b) << 16);
}

#define LDSM4(r0, r1, r2, r3, addr)                                          \
    asm volatile("ldmatrix.sync.aligned.m8n8.x4.shared.b16 {%0,%1,%2,%3}, [%4];" \
                 : "=r"(r0), "=r"(r1), "=r"(r2), "=r"(r3) : "r"(addr))

#define MMA16816(d, a, b0, b1)                                               \
    asm volatile("mma.sync.aligned.m16n8k16.row.col.f32.bf16.bf16.f32 "      \
                 "{%0,%1,%2,%3},{%4,%5,%6,%7},{%8,%9},{%0,%1,%2,%3};"        \
                 : "+f"((d)[0]), "+f"((d)[1]), "+f"((d)[2]), "+f"((d)[3])    \
                 : "r"((a)[0]), "r"((a)[1]), "r"((a)[2]), "r"((a)[3]),       \
                   "r"(b0), "r"(b1))

// ---------------- tiny kernels ----------------
__global__ void zero_kernel() {
    int stride = gridDim.x * blockDim.x;
    int tid = blockIdx.x * blockDim.x + threadIdx.x;
    for (int i = tid; i < NN * DD; i += stride) g_agg[i] = 0.0f;
    for (int i = tid; i < NN; i += stride) g_cnt[i] = 0.0f;
}
__global__ void rinv_kernel() {
    int i = blockIdx.x * blockDim.x + threadIdx.x;
    if (i < NN) g_cnt[i] = 1.0f / fmaxf(g_cnt[i], 1.0f);
}
// transpose W[k][n] f32 -> [n][k] bf16 hi/lo
__global__ void prep_kernel(const float* __restrict__ W1, const float* __restrict__ W2) {
    int t = blockIdx.x * blockDim.x + threadIdx.x;
    if (t >= 2 * 64 * 256) return;
    int n = t & 255;
    int k0 = ((t >> 8) & 63) * 8;
    int w = t >> 14;
    const float* W = w ? W2 : W1;
#pragma unroll
    for (int i = 0; i < 8; i++) {
        int k = k0 + i;
        float v = W[(size_t)k * DD + n];
        __nv_bfloat16 h = __float2bfloat16(v);
        float r = v - __bfloat162float(h);
        size_t o = ((size_t)w * 256 + n) * KW + k;
        g_wh[o] = __bfloat16_as_ushort(h);
        g_wl[o] = __bfloat16_as_ushort(__float2bfloat16(r));
    }
}

// ---------------- HMMA GEMM ----------------
// CTA tile 128(M) x 128(N); gridDim.x = 2 N-halves (fast-varying, L2 A-reuse)
// MODE 0: g_xa = x @ W1a + b1                                 (M=NN, K=256)
// MODE 1: h = relu(ea @ W1b + g_xa[row]); red into g_agg[col] (M=NE, K=256)
// MODE 2: out = relu(x @ W2a + (agg*rinv) @ W2b + b2)         (M=NN, K=512)
template <int MODE>
__global__ __launch_bounds__(256, 2)
void gemm_kernel(const float* __restrict__ x, const float* __restrict__ ea,
                 const int* __restrict__ eidx, const float* __restrict__ bias,
                 float* __restrict__ outp)
{
    // smem: A 128x16 bf16 (hi,lo planes), B 128x16 bf16 (hi,lo planes), swizzled
    __shared__ __align__(16) unsigned char sA[2][4096];
    __shared__ __align__(16) unsigned char sB[2][4096];
    __shared__ int rs[128], cs[128];
    __shared__ float srv[128];

    const int tid = threadIdx.x, lane = tid & 31, wid = tid >> 5;
    const int wm = wid >> 1, wn = wid & 1;   // warp grid 4(M) x 2(N), warp tile 32x64
    const int n0 = blockIdx.x * 128;         // N-half
    const int m0 = blockIdx.y * 128;

    if (MODE == 1 && tid < 128) {
        int e = min(m0 + tid, NE - 1);
        rs[tid] = eidx[e];
        cs[tid] = eidx[NE + e];
    }
    if (MODE == 2 && tid < 128) {
        int m = m0 + tid;
        srv[tid] = (m < NN) ? g_cnt[m] : 0.0f;
    }

    const uint32_t sAb[2] = { smem_u32(sA[0]), smem_u32(sA[1]) };
    const uint32_t sBb[2] = { smem_u32(sB[0]), smem_u32(sB[1]) };

    float4 aST[2];
    uint4  bST[2];

    auto loadStage = [&](int ks) {
        // A: 128 rows x 16 k f32 -> 512 float4, 2 per thread
#pragma unroll
        for (int j = 0; j < 2; j++) {
            int idx = tid + j * 256;
            int row = idx >> 2, kk = idx & 3;
            if (MODE == 1) {
                int gm = min(m0 + row, NE - 1);
                aST[j] = *(const float4*)&ea[(size_t)gm * DD + ks * 16 + kk * 4];
            } else if (MODE == 0) {
                int gm = min(m0 + row, NN - 1);
                aST[j] = *(const float4*)&x[(size_t)gm * DD + ks * 16 + kk * 4];
            } else {
                int gm = min(m0 + row, NN - 1);
                if (ks < 16) {
                    aST[j] = *(const float4*)&x[(size_t)gm * DD + ks * 16 + kk * 4];
                } else {
                    float4 v = *(const float4*)&g_agg[(size_t)gm * DD + (ks - 16) * 16 + kk * 4];
                    float s = srv[row];
                    v.x *= s; v.y *= s; v.z *= s; v.w *= s;
                    aST[j] = v;
                }
            }
        }
        // B: 128 n-rows x 16 k bf16, hi+lo: one uint4 per plane per thread
        const int w  = (MODE == 2) ? 1 : 0;
        const int kb = (MODE == 1) ? 256 + ks * 16 : ks * 16;
        {
            int n = tid >> 1, c = tid & 1;
            size_t o = ((size_t)w * 256 + n0 + n) * KW + kb + c * 8;
            bST[0] = *(const uint4*)&g_wh[o];
            bST[1] = *(const uint4*)&g_wl[o];
        }
    };
    auto storeStage = [&]() {
#pragma unroll
        for (int j = 0; j < 2; j++) {
            int idx = tid + j * 256;
            int row = idx >> 2, kk = idx & 3;
            int c = kk >> 1;
            uint32_t off = row * 32 + (((c ^ ((row >> 2) & 1)) << 4)) + (kk & 1) * 8;
            float4 v = aST[j];
            __nv_bfloat16 h0 = __float2bfloat16(v.x), h1 = __float2bfloat16(v.y);
            __nv_bfloat16 h2 = __float2bfloat16(v.z), h3 = __float2bfloat16(v.w);
            __nv_bfloat16 l0 = __float2bfloat16(v.x - __bfloat162float(h0));
            __nv_bfloat16 l1 = __float2bfloat16(v.y - __bfloat162float(h1));
            __nv_bfloat16 l2 = __float2bfloat16(v.z - __bfloat162float(h2));
            __nv_bfloat16 l3 = __float2bfloat16(v.w - __bfloat162float(h3));
            *(uint2*)(sA[0] + off) = make_uint2(pack2(h0, h1), pack2(h2, h3));
            *(uint2*)(sA[1] + off) = make_uint2(pack2(l0, l1), pack2(l2, l3));
        }
        {
            int n = tid >> 1, c = tid & 1;
            uint32_t off = n * 32 + ((c ^ ((n >> 2) & 1)) << 4);
            *(uint4*)(sB[0] + off) = bST[0];
            *(uint4*)(sB[1] + off) = bST[1];
        }
    };

    float acc[2][8][4];
#pragma unroll
    for (int a = 0; a < 2; a++)
#pragma unroll
        for (int b = 0; b < 8; b++)
#pragma unroll
            for (int q = 0; q < 4; q++) acc[a][b][q] = 0.0f;

    auto compute = [&]() {
#pragma unroll
        for (int sp = 0; sp < 3; sp++) {
            const uint32_t Ab = sAb[sp == 2 ? 1 : 0];
            const uint32_t Bb = sBb[sp == 1 ? 1 : 0];
            uint32_t afr[2][4];
#pragma unroll
            for (int mi = 0; mi < 2; mi++) {
                int row = wm * 32 + mi * 16 + (lane & 7) + ((lane >> 3) & 1) * 8;
                int c = lane >> 4;
                uint32_t addr = Ab + row * 32 + ((c ^ ((row >> 2) & 1)) << 4);
                LDSM4(afr[mi][0], afr[mi][1], afr[mi][2], afr[mi][3], addr);
            }
#pragma unroll
            for (int np = 0; np < 4; np++) {
                int n = wn * 64 + np * 16 + (lane & 7) + ((lane >> 4) & 1) * 8;
                int c = (lane >> 3) & 1;
                uint32_t addr = Bb + n * 32 + ((c ^ ((n >> 2) & 1)) << 4);
                uint32_t bfr[4];
                LDSM4(bfr[0], bfr[1], bfr[2], bfr[3], addr);
#pragma unroll
                for (int mi = 0; mi < 2; mi++) {
                    MMA16816(acc[mi][np * 2 + 0], afr[mi], bfr[0], bfr[1]);
                    MMA16816(acc[mi][np * 2 + 1], afr[mi], bfr[2], bfr[3]);
                }
            }
        }
    };

    const int NK = (MODE == 2) ? 32 : 16;
    loadStage(0);
    for (int ks = 0; ks < NK; ks++) {
        storeStage();
        __syncthreads();
        if (ks + 1 < NK) loadStage(ks + 1);
        compute();
        __syncthreads();
    }

    // ---------------- epilogue ----------------
    const int colb = n0 + wn * 64 + (lane & 3) * 2;
    if (MODE == 1) {
#pragma unroll
        for (int mi = 0; mi < 2; mi++) {
#pragma unroll
            for (int h = 0; h < 2; h++) {
                int lr = wm * 32 + mi * 16 + (lane >> 2) + h * 8;
                bool valid = (m0 + lr < NE);
                if (!valid) continue;
                int srcr = rs[lr], dstc = cs[lr];
                const float* xr = &g_xa[(size_t)srcr * DD];
                float* ag = &g_agg[(size_t)dstc * DD];
#pragma unroll
                for (int nt = 0; nt < 8; nt++) {
                    int n = colb + nt * 8;
                    float2 xv = *(const float2*)&xr[n];
                    float v0 = fmaxf(acc[mi][nt][h * 2 + 0] + xv.x, 0.0f);
                    float v1 = fmaxf(acc[mi][nt][h * 2 + 1] + xv.y, 0.0f);
                    asm volatile("red.global.add.v2.f32 [%0], {%1,%2};"
                                 :: "l"(ag + n), "f"(v0), "f"(v1) : "memory");
                }
            }
        }
        if (blockIdx.x == 0 && tid < 128 && m0 + tid < NE)
            atomicAdd(&g_cnt[cs[tid]], 1.0f);
    } else {
#pragma unroll
        for (int mi = 0; mi < 2; mi++) {
#pragma unroll
            for (int h = 0; h < 2; h++) {
                int row = m0 + wm * 32 + mi * 16 + (lane >> 2) + h * 8;
                if (row >= NN) continue;
                float* dst = (MODE == 0) ? &g_xa[(size_t)row * DD] : &outp[(size_t)row * DD];
#pragma unroll
                for (int nt = 0; nt < 8; nt++) {
                    int n = colb + nt * 8;
                    float2 bb = *(const float2*)&bias[n];
                    float2 v;
                    v.x = acc[mi][nt][h * 2 + 0] + bb.x;
                    v.y = acc[mi][nt][h * 2 + 1] + bb.y;
                    if (MODE == 2) { v.x = fmaxf(v.x, 0.0f); v.y = fmaxf(v.y, 0.0f); }
                    *(float2*)&dst[n] = v;
                }
            }
        }
    }
}

// ---------------------------------------------------------------------------
extern "C" void kernel_launch(void* const* d_in, const int* in_sizes, int n_in,
                              void* d_out, int out_size) {
    const float* x  = (const float*)d_in[0];
    const int* eix  = (const int*)d_in[1];   // int32 (jax x64 disabled)
    const float* ea = (const float*)d_in[2];
    const float* W1 = (const float*)d_in[5];
    const float* b1 = (const float*)d_in[6];
    const float* W2 = (const float*)d_in[7];
    const float* b2 = (const float*)d_in[8];
    float* out      = (float*)d_out;
    (void)in_sizes; (void)n_in; (void)out_size;

    zero_kernel<<<2048, 256>>>();
    prep_kernel<<<128, 256>>>(W1, W2);
    dim3 gN(2, (NN + 127) / 128);
    dim3 gE(2, (NE + 127) / 128);
    gemm_kernel<0><<<gN, 256>>>(x, ea, eix, b1, nullptr);
    gemm_kernel<1><<<gE, 256>>>(x, ea, eix, b1, nullptr);
    rinv_kernel<<<(NN + 255) / 256, 256>>>();
    gemm_kernel<2><<<gN, 256>>>(x, ea, eix, b2, out);
}